// round 2
// baseline (speedup 1.0000x reference)
#include <cuda_runtime.h>
#include <math.h>

#define LSEQ 262144
#define NMODE 64
#define TCH 64
#define NCHUNK (LSEQ / TCH)                 // 4096
#define WARPS_PER_BLOCK 8
#define BLOCK_THREADS (WARPS_PER_BLOCK * 32)
#define GRID_AC (NCHUNK / WARPS_PER_BLOCK)  // 512

// Per-mode constants (filled by setup_kernel, double-precision path)
__device__ float g_zre[NMODE], g_zim[NMODE];    // z = exp(dt*A)
__device__ float g_z2re[NMODE], g_z2im[NMODE];  // z^2
__device__ float g_cfre[NMODE], g_cfim[NMODE];  // coeff = Ct*(z-1)/A
__device__ float g_wre[NMODE], g_wim[NMODE];    // w = z^TCH
__device__ float g_w4re[NMODE], g_w4im[NMODE];  // w^4
// Chunk partials / carries: [mode][chunk]
__device__ float g_Pre[NMODE * NCHUNK], g_Pim[NMODE * NCHUNK];
__device__ float g_Cre[NMODE * NCHUNK], g_Cim[NMODE * NCHUNK];

__global__ void setup_kernel(const float* __restrict__ A_re,
                             const float* __restrict__ A_im,
                             const float* __restrict__ C,
                             const float* __restrict__ log_step) {
    int n = threadIdx.x;
    if (n >= NMODE) return;
    double dt  = exp((double)log_step[0]);
    double ar  = (double)A_re[n], ai = (double)A_im[n];
    double dre = dt * ar, dim = dt * ai;
    double e   = exp(dre);
    double zre = e * cos(dim), zim = e * sin(dim);
    // coeff = Ct * (z - 1) / A
    double nre = zre - 1.0, nim = zim;
    double inv = 1.0 / (ar * ar + ai * ai);
    double tre = (nre * ar + nim * ai) * inv;
    double tim = (nim * ar - nre * ai) * inv;
    double cr  = (double)C[2 * n], ci = (double)C[2 * n + 1];
    g_cfre[n] = (float)(cr * tre - ci * tim);
    g_cfim[n] = (float)(cr * tim + ci * tre);
    g_zre[n]  = (float)zre;
    g_zim[n]  = (float)zim;
    double e2 = exp(2.0 * dre);
    g_z2re[n] = (float)(e2 * cos(2.0 * dim));
    g_z2im[n] = (float)(e2 * sin(2.0 * dim));
    double ew = exp((double)TCH * dre);
    double wa = (double)TCH * dim;
    g_wre[n]  = (float)(ew * cos(wa));
    g_wim[n]  = (float)(ew * sin(wa));
    double ew4 = exp(4.0 * (double)TCH * dre);
    double wa4 = 4.0 * (double)TCH * dim;
    g_w4re[n]  = (float)(ew4 * cos(wa4));
    g_w4im[n]  = (float)(ew4 * sin(wa4));
}

// Phase 1: per-chunk local recurrence (2-step unrolled) -> chunk partials.
// One warp per chunk; each lane owns modes (lane, lane+32).
__global__ __launch_bounds__(BLOCK_THREADS) void partial_kernel(const float* __restrict__ u) {
    __shared__ float su[WARPS_PER_BLOCK * TCH];
    int tid  = threadIdx.x;
    int base = blockIdx.x * (WARPS_PER_BLOCK * TCH);
#pragma unroll
    for (int i = 0; i < (WARPS_PER_BLOCK * TCH) / BLOCK_THREADS; i++)
        su[tid + i * BLOCK_THREADS] = u[base + tid + i * BLOCK_THREADS];
    __syncthreads();

    int warp = tid >> 5, lane = tid & 31;
    int chunk = blockIdx.x * WARPS_PER_BLOCK + warp;
    int m0 = lane, m1 = lane + 32;
    float z0r = g_zre[m0],  z0i = g_zim[m0];
    float z1r = g_zre[m1],  z1i = g_zim[m1];
    float w0r = g_z2re[m0], w0i = g_z2im[m0];
    float w1r = g_z2re[m1], w1i = g_z2im[m1];
    float s0r = 0.f, s0i = 0.f, s1r = 0.f, s1i = 0.f;
    const float* uw = &su[warp * TCH];
#pragma unroll
    for (int i = 0; i < TCH; i += 2) {
        float u1 = uw[i], u2 = uw[i + 1];
        // b = z*u1 + u2 (off critical path)
        float b0r = fmaf(z0r, u1, u2), b0i = z0i * u1;
        float b1r = fmaf(z1r, u1, u2), b1i = z1i * u1;
        // s <- z^2*s + b  (critical path: 2 dependent FMAs per 2 elements)
        float n0r = fmaf(w0r, s0r, fmaf(-w0i, s0i, b0r));
        float n0i = fmaf(w0i, s0r, fmaf( w0r, s0i, b0i));
        float n1r = fmaf(w1r, s1r, fmaf(-w1i, s1i, b1r));
        float n1i = fmaf(w1i, s1r, fmaf( w1r, s1i, b1i));
        s0r = n0r; s0i = n0i; s1r = n1r; s1i = n1i;
    }
    g_Pre[m0 * NCHUNK + chunk] = s0r;  g_Pim[m0 * NCHUNK + chunk] = s0i;
    g_Pre[m1 * NCHUNK + chunk] = s1r;  g_Pim[m1 * NCHUNK + chunk] = s1i;
}

// Phase 2: per-mode scan over 4096 chunk partials.
// Each thread folds 4 chunks (Horner with w); Hillis-Steele over 1024 with W = w^4.
__global__ __launch_bounds__(1024) void scan_kernel() {
    __shared__ float sre[1024], sim_[1024];
    int mode = blockIdx.x, t = threadIdx.x;
    float wr = g_wre[mode], wi = g_wim[mode];
    const float* Pr = &g_Pre[mode * NCHUNK];
    const float* Pi = &g_Pim[mode * NCHUNK];
    float p0r = Pr[4 * t],     p0i = Pi[4 * t];
    float p1r = Pr[4 * t + 1], p1i = Pi[4 * t + 1];
    float p2r = Pr[4 * t + 2], p2i = Pi[4 * t + 2];
    float p3r = Pr[4 * t + 3], p3i = Pi[4 * t + 3];
    // Horner fold: v = ((p0*w + p1)*w + p2)*w + p3
    float vr = p0r, vi = p0i;
    float nr = fmaf(wr, vr, fmaf(-wi, vi, p1r));
    float ni = fmaf(wi, vr, fmaf( wr, vi, p1i));
    vr = nr; vi = ni;
    nr = fmaf(wr, vr, fmaf(-wi, vi, p2r));
    ni = fmaf(wi, vr, fmaf( wr, vi, p2i));
    vr = nr; vi = ni;
    nr = fmaf(wr, vr, fmaf(-wi, vi, p3r));
    ni = fmaf(wi, vr, fmaf( wr, vi, p3i));
    vr = nr; vi = ni;
    sre[t] = vr; sim_[t] = vi;
    float cwr = g_w4re[mode], cwi = g_w4im[mode];  // W = w^4
    __syncthreads();
    for (int k = 1; k < 1024; k <<= 1) {
        float ore = 0.f, oim = 0.f;
        if (t >= k) { ore = sre[t - k]; oim = sim_[t - k]; }
        __syncthreads();
        vr += cwr * ore - cwi * oim;
        vi += cwr * oim + cwi * ore;
        sre[t] = vr; sim_[t] = vi;
        float nwr = cwr * cwr - cwi * cwi;
        cwi = 2.f * cwr * cwi; cwr = nwr;
        __syncthreads();
    }
    // Exclusive carries for chunks 4t..4t+3.
    float e0r = 0.f, e0i = 0.f;
    if (t > 0) { e0r = sre[t - 1]; e0i = sim_[t - 1]; }
    float* Cr = &g_Cre[mode * NCHUNK];
    float* Ci = &g_Cim[mode * NCHUNK];
    Cr[4 * t] = e0r;  Ci[4 * t] = e0i;
    float e1r = fmaf(wr, e0r, fmaf(-wi, e0i, p0r));
    float e1i = fmaf(wi, e0r, fmaf( wr, e0i, p0i));
    Cr[4 * t + 1] = e1r;  Ci[4 * t + 1] = e1i;
    float e2r = fmaf(wr, e1r, fmaf(-wi, e1i, p1r));
    float e2i = fmaf(wi, e1r, fmaf( wr, e1i, p1i));
    Cr[4 * t + 2] = e2r;  Ci[4 * t + 2] = e2i;
    float e3r = fmaf(wr, e2r, fmaf(-wi, e2i, p2r));
    float e3i = fmaf(wi, e2r, fmaf( wr, e2i, p2i));
    Cr[4 * t + 3] = e3r;  Ci[4 * t + 3] = e3i;
}

// Phase 3: re-run recurrence (2-step unrolled) seeded with carries, emit y.
__global__ __launch_bounds__(BLOCK_THREADS) void output_kernel(const float* __restrict__ u,
                                                               const float* __restrict__ D,
                                                               float* __restrict__ y) {
    __shared__ float su[WARPS_PER_BLOCK * TCH];
    __shared__ float red[WARPS_PER_BLOCK][32 * 33];
    int tid  = threadIdx.x;
    int base = blockIdx.x * (WARPS_PER_BLOCK * TCH);
#pragma unroll
    for (int i = 0; i < (WARPS_PER_BLOCK * TCH) / BLOCK_THREADS; i++)
        su[tid + i * BLOCK_THREADS] = u[base + tid + i * BLOCK_THREADS];
    __syncthreads();

    int warp = tid >> 5, lane = tid & 31;
    int chunk = blockIdx.x * WARPS_PER_BLOCK + warp;
    int m0 = lane, m1 = lane + 32;
    float z0r = g_zre[m0],  z0i = g_zim[m0];
    float z1r = g_zre[m1],  z1i = g_zim[m1];
    float w0r = g_z2re[m0], w0i = g_z2im[m0];
    float w1r = g_z2re[m1], w1i = g_z2im[m1];
    float f0r = g_cfre[m0], f0i = g_cfim[m0];
    float f1r = g_cfre[m1], f1i = g_cfim[m1];
    float s0r = g_Cre[m0 * NCHUNK + chunk], s0i = g_Cim[m0 * NCHUNK + chunk];
    float s1r = g_Cre[m1 * NCHUNK + chunk], s1i = g_Cim[m1 * NCHUNK + chunk];
    float Dv = D[0];
    const float* uw = &su[warp * TCH];
    float* rw = &red[warp][0];
    int gbase = base + warp * TCH;

#pragma unroll
    for (int tile = 0; tile < TCH / 32; tile++) {
#pragma unroll
        for (int i = 0; i < 32; i += 2) {
            float u1 = uw[tile * 32 + i], u2 = uw[tile * 32 + i + 1];
            // odd state t = z*s + u1 (off critical path)
            float t0r = fmaf(z0r, s0r, fmaf(-z0i, s0i, u1));
            float t0i = fmaf(z0i, s0r, z0r * s0i);
            float t1r = fmaf(z1r, s1r, fmaf(-z1i, s1i, u1));
            float t1i = fmaf(z1i, s1r, z1r * s1i);
            // even state v = z^2*s + (z*u1 + u2)  (critical path)
            float b0r = fmaf(z0r, u1, u2), b0i = z0i * u1;
            float b1r = fmaf(z1r, u1, u2), b1i = z1i * u1;
            float v0r = fmaf(w0r, s0r, fmaf(-w0i, s0i, b0r));
            float v0i = fmaf(w0i, s0r, fmaf( w0r, s0i, b0i));
            float v1r = fmaf(w1r, s1r, fmaf(-w1i, s1i, b1r));
            float v1i = fmaf(w1i, s1r, fmaf( w1r, s1i, b1i));
            s0r = v0r; s0i = v0i; s1r = v1r; s1i = v1i;
            // contributions: Re(coeff*state) summed over this lane's 2 modes
            float c1 = fmaf(f0r, t0r, fmaf(-f0i, t0i, fmaf(f1r, t1r, -f1i * t1i)));
            float c2 = fmaf(f0r, v0r, fmaf(-f0i, v0i, fmaf(f1r, v1r, -f1i * v1i)));
            rw[lane * 33 + i]     = c1;
            rw[lane * 33 + i + 1] = c2;
        }
        __syncwarp();
        float acc = 0.f;
#pragma unroll
        for (int l = 0; l < 32; l++) acc += rw[l * 33 + lane];
        float uv = uw[tile * 32 + lane];
        y[gbase + tile * 32 + lane] = fmaf(Dv, uv, acc);
        __syncwarp();
    }
}

extern "C" void kernel_launch(void* const* d_in, const int* in_sizes, int n_in,
                              void* d_out, int out_size) {
    const float* u        = (const float*)d_in[0];
    const float* A_re     = (const float*)d_in[1];
    const float* A_im     = (const float*)d_in[2];
    const float* C        = (const float*)d_in[3];
    const float* D        = (const float*)d_in[4];
    const float* log_step = (const float*)d_in[5];
    float* y = (float*)d_out;

    setup_kernel<<<1, NMODE>>>(A_re, A_im, C, log_step);
    partial_kernel<<<GRID_AC, BLOCK_THREADS>>>(u);
    scan_kernel<<<NMODE, 1024>>>();
    output_kernel<<<GRID_AC, BLOCK_THREADS>>>(u, D, y);
}

// round 3
// speedup vs baseline: 1.2108x; 1.2108x over previous
#include <cuda_runtime.h>
#include <math.h>

#define LSEQ 262144
#define NMODE 64
#define TCH 128
#define NCHUNK (LSEQ / TCH)         // 2048
#define WPB 8
#define BTH 256
#define GRID_AC (NCHUNK / WPB)      // 256

typedef unsigned long long u64;

// Per-mode constants (double-precision setup)
__device__ float g_zre[NMODE], g_zim[NMODE];    // z = exp(dt*A)
__device__ float g_z2re[NMODE], g_z2im[NMODE];  // z^2
__device__ float g_cfre[NMODE], g_cfim[NMODE];  // coeff = Ct*(z-1)/A
__device__ float g_wre[NMODE], g_wim[NMODE];    // w = z^TCH
__device__ float g_w2re[NMODE], g_w2im[NMODE];  // w^2
// Intermediates, [mode][chunk], interleaved complex for 16B access
__device__ __align__(16) float2 g_P[NMODE * NCHUNK];
__device__ __align__(16) float2 g_C[NMODE * NCHUNK];

// ---- packed f32x2 helpers ----
__device__ __forceinline__ u64 pk2(float lo, float hi) {
    u64 r; asm("mov.b64 %0, {%1,%2};" : "=l"(r) : "f"(lo), "f"(hi)); return r;
}
__device__ __forceinline__ void upk2(u64 v, float& lo, float& hi) {
    asm("mov.b64 {%0,%1}, %2;" : "=f"(lo), "=f"(hi) : "l"(v));
}
__device__ __forceinline__ u64 fma2(u64 a, u64 b, u64 c) {
    u64 d; asm("fma.rn.f32x2 %0, %1, %2, %3;" : "=l"(d) : "l"(a), "l"(b), "l"(c)); return d;
}
__device__ __forceinline__ u64 mul2(u64 a, u64 b) {
    u64 d; asm("mul.rn.f32x2 %0, %1, %2;" : "=l"(d) : "l"(a), "l"(b)); return d;
}

__global__ void setup_kernel(const float* __restrict__ A_re,
                             const float* __restrict__ A_im,
                             const float* __restrict__ C,
                             const float* __restrict__ log_step) {
    int n = threadIdx.x;
    if (n >= NMODE) return;
    double dt  = exp((double)log_step[0]);
    double ar  = (double)A_re[n], ai = (double)A_im[n];
    double dre = dt * ar, dim = dt * ai;
    double e   = exp(dre);
    double zre = e * cos(dim), zim = e * sin(dim);
    double nre = zre - 1.0, nim = zim;
    double inv = 1.0 / (ar * ar + ai * ai);
    double tre = (nre * ar + nim * ai) * inv;
    double tim = (nim * ar - nre * ai) * inv;
    double cr  = (double)C[2 * n], ci = (double)C[2 * n + 1];
    g_cfre[n] = (float)(cr * tre - ci * tim);
    g_cfim[n] = (float)(cr * tim + ci * tre);
    g_zre[n]  = (float)zre;
    g_zim[n]  = (float)zim;
    double e2 = exp(2.0 * dre);
    g_z2re[n] = (float)(e2 * cos(2.0 * dim));
    g_z2im[n] = (float)(e2 * sin(2.0 * dim));
    double ew = exp((double)TCH * dre), wa = (double)TCH * dim;
    g_wre[n]  = (float)(ew * cos(wa));
    g_wim[n]  = (float)(ew * sin(wa));
    double ew2 = exp(2.0 * (double)TCH * dre), wa2 = 2.0 * (double)TCH * dim;
    g_w2re[n]  = (float)(ew2 * cos(wa2));
    g_w2im[n]  = (float)(ew2 * sin(wa2));
}

// Phase 1: per-chunk recurrence (f32x2 packed over this lane's 2 modes),
// smem transpose, coalesced 16B stores into [mode][chunk] layout.
__global__ __launch_bounds__(BTH) void partial_kernel(const float* __restrict__ u) {
    __shared__ __align__(16) float su[WPB * TCH];
    __shared__ __align__(16) float2 sP[NMODE][WPB];
    int tid  = threadIdx.x;
    int base = blockIdx.x * (WPB * TCH);
    ((float4*)su)[tid] = ((const float4*)(u + base))[tid];
    __syncthreads();

    int warp = tid >> 5, lane = tid & 31;
    u64 zr  = pk2(g_zre[lane],  g_zre[lane + 32]);
    u64 zi  = pk2(g_zim[lane],  g_zim[lane + 32]);
    u64 wr  = pk2(g_z2re[lane], g_z2re[lane + 32]);
    float w2i0 = g_z2im[lane], w2i1 = g_z2im[lane + 32];
    u64 wi  = pk2(w2i0, w2i1);
    u64 nwi = pk2(-w2i0, -w2i1);
    u64 sr = pk2(0.f, 0.f), si = pk2(0.f, 0.f);
    const float2* uw = (const float2*)&su[warp * TCH];
#pragma unroll 16
    for (int i = 0; i < TCH / 2; i++) {
        float2 uu = uw[i];
        u64 u1 = pk2(uu.x, uu.x), u2 = pk2(uu.y, uu.y);
        u64 br = fma2(zr, u1, u2);           // b = z*u1 + u2 (off chain)
        u64 bi = mul2(zi, u1);
        u64 nr = fma2(wr, sr, fma2(nwi, si, br));  // s <- z^2*s + b
        u64 ni = fma2(wi, sr, fma2(wr, si, bi));
        sr = nr; si = ni;
    }
    float s0r, s1r, s0i, s1i;
    upk2(sr, s0r, s1r); upk2(si, s0i, s1i);
    sP[lane][warp]      = make_float2(s0r, s0i);
    sP[lane + 32][warp] = make_float2(s1r, s1i);
    __syncthreads();
    int row = tid >> 2, col = (tid & 3) * 2;
    int c0  = blockIdx.x * WPB;
    *(float4*)&g_P[row * NCHUNK + c0 + col] = *(const float4*)&sP[row][col];
}

// Phase 2: per-mode scan over 2048 chunk partials (pairs folded, W = w^2).
__global__ __launch_bounds__(1024) void scan_kernel() {
    __shared__ float sre[1024], sim_[1024];
    int mode = blockIdx.x, t = threadIdx.x;
    float wr = g_wre[mode], wi = g_wim[mode];
    const float2* P = &g_P[mode * NCHUNK];
    float4 pp = *(const float4*)&P[2 * t];     // (p0.re,p0.im,p1.re,p1.im)
    float p0r = pp.x, p0i = pp.y, p1r = pp.z, p1i = pp.w;
    float vr = fmaf(wr, p0r, fmaf(-wi, p0i, p1r));
    float vi = fmaf(wi, p0r, fmaf(wr, p0i, p1i));
    sre[t] = vr; sim_[t] = vi;
    float cwr = g_w2re[mode], cwi = g_w2im[mode];
    __syncthreads();
    for (int k = 1; k < 1024; k <<= 1) {
        float ore = 0.f, oim = 0.f;
        if (t >= k) { ore = sre[t - k]; oim = sim_[t - k]; }
        __syncthreads();
        vr += cwr * ore - cwi * oim;
        vi += cwr * oim + cwi * ore;
        sre[t] = vr; sim_[t] = vi;
        float nwr = cwr * cwr - cwi * cwi;
        cwi = 2.f * cwr * cwi; cwr = nwr;
        __syncthreads();
    }
    float e0r = 0.f, e0i = 0.f;
    if (t > 0) { e0r = sre[t - 1]; e0i = sim_[t - 1]; }
    float e1r = fmaf(wr, e0r, fmaf(-wi, e0i, p0r));
    float e1i = fmaf(wi, e0r, fmaf(wr, e0i, p0i));
    float4 cc = make_float4(e0r, e0i, e1r, e1i);
    *(float4*)&g_C[mode * NCHUNK + 2 * t] = cc;
}

// Phase 3: carry-seeded recurrence (f32x2), transpose-reduce, emit y.
__global__ __launch_bounds__(BTH) void output_kernel(const float* __restrict__ u,
                                                     const float* __restrict__ D,
                                                     float* __restrict__ y) {
    __shared__ __align__(16) float su[WPB * TCH];
    __shared__ __align__(16) float2 sC[NMODE][WPB];
    __shared__ __align__(16) float red[WPB][32 * 34];
    int tid  = threadIdx.x;
    int base = blockIdx.x * (WPB * TCH);
    ((float4*)su)[tid] = ((const float4*)(u + base))[tid];
    {   // cooperative coalesced carry load for this block's 8 chunks
        int row = tid >> 2, col = (tid & 3) * 2;
        int c0  = blockIdx.x * WPB;
        *(float4*)&sC[row][col] = *(const float4*)&g_C[row * NCHUNK + c0 + col];
    }
    __syncthreads();

    int warp = tid >> 5, lane = tid & 31;
    u64 zr  = pk2(g_zre[lane],  g_zre[lane + 32]);
    float zi0 = g_zim[lane], zi1 = g_zim[lane + 32];
    u64 zi  = pk2(zi0, zi1);
    u64 nzi = pk2(-zi0, -zi1);
    u64 wr  = pk2(g_z2re[lane], g_z2re[lane + 32]);
    float wi0 = g_z2im[lane], wi1 = g_z2im[lane + 32];
    u64 wi  = pk2(wi0, wi1);
    u64 nwi = pk2(-wi0, -wi1);
    u64 fr  = pk2(g_cfre[lane], g_cfre[lane + 32]);
    float fi0 = g_cfim[lane], fi1 = g_cfim[lane + 32];
    u64 nfi = pk2(-fi0, -fi1);
    float2 car0 = sC[lane][warp], car1 = sC[lane + 32][warp];
    u64 sr = pk2(car0.x, car1.x), si = pk2(car0.y, car1.y);
    float Dv = D[0];
    const float2* uw = (const float2*)&su[warp * TCH];
    float* rw = &red[warp][0];
    int gbase = base + warp * TCH;

    for (int tile = 0; tile < TCH / 32; tile++) {
#pragma unroll
        for (int i = 0; i < 32; i += 2) {
            float2 uu = uw[(tile * 32 + i) >> 1];
            u64 u1 = pk2(uu.x, uu.x), u2 = pk2(uu.y, uu.y);
            // odd state t = z*s + u1
            u64 tr = fma2(zr, sr, fma2(nzi, si, u1));
            u64 ti = fma2(zi, sr, mul2(zr, si));
            // even state v = z^2*s + (z*u1 + u2)
            u64 br = fma2(zr, u1, u2);
            u64 bi = mul2(zi, u1);
            u64 vr = fma2(wr, sr, fma2(nwi, si, br));
            u64 vi = fma2(wi, sr, fma2(wr, si, bi));
            sr = vr; si = vi;
            // contributions Re(coeff*state), packed over 2 modes -> horizontal add
            u64 cp1 = fma2(fr, tr, mul2(nfi, ti));
            u64 cp2 = fma2(fr, vr, mul2(nfi, vi));
            float a0, a1, b0, b1;
            upk2(cp1, a0, a1); upk2(cp2, b0, b1);
            float2 cc = make_float2(a0 + a1, b0 + b1);
            *(float2*)&rw[lane * 34 + i] = cc;   // 8B aligned (34 even)
        }
        __syncwarp();
        float acc = 0.f;
#pragma unroll
        for (int l = 0; l < 32; l++) acc += rw[l * 34 + lane];
        float uv = su[warp * TCH + tile * 32 + lane];
        y[gbase + tile * 32 + lane] = fmaf(Dv, uv, acc);
        __syncwarp();
    }
}

extern "C" void kernel_launch(void* const* d_in, const int* in_sizes, int n_in,
                              void* d_out, int out_size) {
    const float* u        = (const float*)d_in[0];
    const float* A_re     = (const float*)d_in[1];
    const float* A_im     = (const float*)d_in[2];
    const float* C        = (const float*)d_in[3];
    const float* D        = (const float*)d_in[4];
    const float* log_step = (const float*)d_in[5];
    float* y = (float*)d_out;

    setup_kernel<<<1, NMODE>>>(A_re, A_im, C, log_step);
    partial_kernel<<<GRID_AC, BTH>>>(u);
    scan_kernel<<<NMODE, 1024>>>();
    output_kernel<<<GRID_AC, BTH>>>(u, D, y);
}